// round 2
// baseline (speedup 1.0000x reference)
#include <cuda_runtime.h>

#define N_NODES 50000
#define N_PAD   50048          // multiple of 128
#define N_EDGES 400000

// ---------------- device scratch (no allocations allowed) ----------------
__device__ float    g_bufA[(size_t)N_PAD * 512];
__device__ float    g_bufB[(size_t)N_PAD * 512];
__device__ float    g_el[N_NODES * 8];
__device__ float    g_er[N_NODES * 8];
__device__ unsigned g_menc[N_NODES * 8];
__device__ float    g_denom[N_NODES * 8];
__device__ float    g_W3[512 * 128];

__device__ __forceinline__ float lrelu(float x) { return x > 0.f ? x : 0.2f * x; }

// order-preserving float <-> uint encoding (for bit-exact atomic max)
__device__ __forceinline__ unsigned fenc(float x) {
    unsigned u = __float_as_uint(x);
    return (u & 0x80000000u) ? ~u : (u | 0x80000000u);
}
__device__ __forceinline__ float fdec(unsigned e) {
    return (e & 0x80000000u) ? __uint_as_float(e & 0x7fffffffu)
                             : __uint_as_float(~e);
}

// ---------------- W3 pad [512,40] -> [512,128] ----------------
__global__ void padW3_kernel(const float* __restrict__ W3) {
    int i = blockIdx.x * blockDim.x + threadIdx.x;
    if (i < 512 * 128) {
        int r = i >> 7, c = i & 127;
        g_W3[i] = (c < 40) ? W3[r * 40 + c] : 0.f;
    }
}

// ---------------- SGEMM: C[N_PAD,M] = A[N_PAD,K] * B[K,M] ----------------
#define BM 128
#define BN 128
#define BK 8
#define TM 8
#define TN 8

__global__ __launch_bounds__(256, 2)
void sgemm_kernel(const float* __restrict__ A, const float* __restrict__ B,
                  float* __restrict__ C, int K, int M) {
    __shared__ float As[BK][BM];
    __shared__ float Bs[BK][BN];
    const int t = threadIdx.x;
    const int rowBase = blockIdx.y * BM;
    const int colBase = blockIdx.x * BN;
    const int arow  = t >> 1;
    const int akoff = (t & 1) * 4;
    const int brow  = t >> 5;
    const int bcol  = (t & 31) * 4;
    const int tx = t & 15;
    const int ty = t >> 4;

    float acc[TM][TN];
    #pragma unroll
    for (int i = 0; i < TM; i++)
        #pragma unroll
        for (int j = 0; j < TN; j++) acc[i][j] = 0.f;

    const float* Aptr = A + (size_t)(rowBase + arow) * K + akoff;

    for (int k0 = 0; k0 < K; k0 += BK) {
        float4 av = *reinterpret_cast<const float4*>(Aptr + k0);
        float4 bv = *reinterpret_cast<const float4*>(
            B + (size_t)(k0 + brow) * M + colBase + bcol);
        As[akoff + 0][arow] = av.x;
        As[akoff + 1][arow] = av.y;
        As[akoff + 2][arow] = av.z;
        As[akoff + 3][arow] = av.w;
        *reinterpret_cast<float4*>(&Bs[brow][bcol]) = bv;
        __syncthreads();
        #pragma unroll
        for (int k = 0; k < BK; k++) {
            float a[TM], b[TN];
            #pragma unroll
            for (int i = 0; i < TM; i++) a[i] = As[k][ty * TM + i];
            #pragma unroll
            for (int j = 0; j < TN; j++) b[j] = Bs[k][tx * TN + j];
            #pragma unroll
            for (int i = 0; i < TM; i++)
                #pragma unroll
                for (int j = 0; j < TN; j++)
                    acc[i][j] = fmaf(a[i], b[j], acc[i][j]);
        }
        __syncthreads();
    }

    #pragma unroll
    for (int i = 0; i < TM; i++) {
        float* Crow = C + (size_t)(rowBase + ty * TM + i) * M + colBase + tx * TN;
        #pragma unroll
        for (int j = 0; j < TN; j += 4) {
            float4 v = make_float4(acc[i][j], acc[i][j + 1], acc[i][j + 2], acc[i][j + 3]);
            *reinterpret_cast<float4*>(Crow + j) = v;
        }
    }
}

// ---------------- per-node attention scores el/er ----------------
template <int H, int D>
__global__ void scores_kernel(const float* __restrict__ feat,
                              const float* __restrict__ al,
                              const float* __restrict__ ar, int ldf) {
    int g = (blockIdx.x * blockDim.x + threadIdx.x) >> 5;
    int lane = threadIdx.x & 31;
    if (g >= N_NODES * H) return;
    int n = g / H, h = g % H;
    const float* f = feat + (size_t)n * ldf + h * D;
    float sl = 0.f, sr = 0.f;
    for (int d = lane; d < D; d += 32) {
        float v = f[d];
        sl = fmaf(v, al[h * D + d], sl);
        sr = fmaf(v, ar[h * D + d], sr);
    }
    #pragma unroll
    for (int off = 16; off; off >>= 1) {
        sl += __shfl_down_sync(0xffffffffu, sl, off);
        sr += __shfl_down_sync(0xffffffffu, sr, off);
    }
    if (lane == 0) { g_el[n * H + h] = sl; g_er[n * H + h] = sr; }
}

// ---------------- edge-parallel softmax stats ----------------
__global__ void init_md_kernel(int count) {
    int i = blockIdx.x * blockDim.x + threadIdx.x;
    if (i < count) {
        g_menc[i] = fenc(-1e30f);
        g_denom[i] = 0.f;
    }
}

template <int H>
__global__ void edge_max_kernel(const int* __restrict__ src, const int* __restrict__ dst) {
    int idx = blockIdx.x * blockDim.x + threadIdx.x;
    if (idx >= N_EDGES * H) return;
    int e = idx / H, h = idx - e * H;
    int s = src[e], d = dst[e];
    float v = lrelu(g_el[s * H + h] + g_er[d * H + h]);
    atomicMax(&g_menc[d * H + h], fenc(v));
}

template <int H>
__global__ void edge_denom_kernel(const int* __restrict__ src, const int* __restrict__ dst) {
    int idx = blockIdx.x * blockDim.x + threadIdx.x;
    if (idx >= N_EDGES * H) return;
    int e = idx / H, h = idx - e * H;
    int s = src[e], d = dst[e];
    float v = lrelu(g_el[s * H + h] + g_er[d * H + h]);
    float m = fdec(g_menc[d * H + h]);
    atomicAdd(&g_denom[d * H + h], __expf(v - m));
}

// ---------------- edge-parallel aggregation: warp per edge ----------------
template <int H, int D, int C>
__global__ void edge_agg_kernel(const float* __restrict__ feat,
                                float* __restrict__ out, int ldf,
                                const int* __restrict__ src,
                                const int* __restrict__ dst) {
    int e = (blockIdx.x * blockDim.x + threadIdx.x) >> 5;
    int lane = threadIdx.x & 31;
    if (e >= N_EDGES) return;
    int s = src[e], d = dst[e];

    float alpha = 0.f;
    if (lane < H) {
        float v = lrelu(g_el[s * H + lane] + g_er[d * H + lane]);
        float m = fdec(g_menc[d * H + lane]);
        float den = g_denom[d * H + lane];
        alpha = __expf(v - m) / den;
    }

    const float4* frow = reinterpret_cast<const float4*>(feat + (size_t)s * ldf);
    float4* orow = reinterpret_cast<float4*>(out + (size_t)d * C);
    constexpr int NQ = C / 4;                 // float4 chunks per row
    #pragma unroll
    for (int q0 = 0; q0 < NQ; q0 += 32) {
        int q = q0 + lane;
        bool ok = (q < NQ);
        int h = ok ? (4 * q) / D : 0;
        float a = __shfl_sync(0xffffffffu, alpha, h);   // all lanes participate
        if (ok) {
            float4 f = frow[q];
            float4 m4 = make_float4(a * f.x, a * f.y, a * f.z, a * f.w);
            atomicAdd(orow + q, m4);          // 128-bit atomic (sm_90+)
        }
    }
}

// ---------------- launch ----------------
extern "C" void kernel_launch(void* const* d_in, const int* in_sizes, int n_in,
                              void* d_out, int out_size) {
    const float* features = (const float*)d_in[0];
    const int*   src      = (const int*)d_in[1];
    const int*   dst      = (const int*)d_in[2];
    const float* W1  = (const float*)d_in[3];
    const float* al1 = (const float*)d_in[4];
    const float* ar1 = (const float*)d_in[5];
    const float* W2  = (const float*)d_in[6];
    const float* al2 = (const float*)d_in[7];
    const float* ar2 = (const float*)d_in[8];
    const float* W3  = (const float*)d_in[9];
    const float* al3 = (const float*)d_in[10];
    const float* ar3 = (const float*)d_in[11];
    float* out = (float*)d_out;

    float *bufA, *bufB, *w3p;
    cudaGetSymbolAddress((void**)&bufA, g_bufA);
    cudaGetSymbolAddress((void**)&bufB, g_bufB);
    cudaGetSymbolAddress((void**)&w3p,  g_W3);

    const int EB8  = (N_EDGES * 8 + 255) / 256;   // edge kernels, H=8
    const int EB1  = (N_EDGES + 255) / 256;       // edge kernels, H=1
    const int AGGB = (N_EDGES * 32 + 255) / 256;  // warp per edge
    const int NMB8 = (N_NODES * 8 + 255) / 256;
    const int NMB1 = (N_NODES + 255) / 256;

    // stage input features into padded scratch
    cudaMemcpyAsync(bufA, features, (size_t)N_NODES * 256 * sizeof(float),
                    cudaMemcpyDeviceToDevice);

    // ---- layer 1: 256 -> 8x64 ----
    sgemm_kernel<<<dim3(512 / BN, N_PAD / BM), 256>>>(bufA, W1, bufB, 256, 512);
    scores_kernel<8, 64><<<N_NODES, 256>>>(bufB, al1, ar1, 512);
    init_md_kernel<<<NMB8, 256>>>(N_NODES * 8);
    edge_max_kernel<8><<<EB8, 256>>>(src, dst);
    edge_denom_kernel<8><<<EB8, 256>>>(src, dst);
    cudaMemsetAsync(bufA, 0, (size_t)N_NODES * 512 * sizeof(float));
    edge_agg_kernel<8, 64, 512><<<AGGB, 256>>>(bufB, bufA, 512, src, dst);

    // ---- layer 2: 8x64 -> 8x64 ----
    sgemm_kernel<<<dim3(512 / BN, N_PAD / BM), 256>>>(bufA, W2, bufB, 512, 512);
    scores_kernel<8, 64><<<N_NODES, 256>>>(bufB, al2, ar2, 512);
    init_md_kernel<<<NMB8, 256>>>(N_NODES * 8);
    edge_max_kernel<8><<<EB8, 256>>>(src, dst);
    edge_denom_kernel<8><<<EB8, 256>>>(src, dst);
    cudaMemsetAsync(bufA, 0, (size_t)N_NODES * 512 * sizeof(float));
    edge_agg_kernel<8, 64, 512><<<AGGB, 256>>>(bufB, bufA, 512, src, dst);

    // ---- layer 3: 8x64 -> 40 (padded to 128 cols) ----
    padW3_kernel<<<(512 * 128 + 255) / 256, 256>>>(W3);
    sgemm_kernel<<<dim3(1, N_PAD / BM), 256>>>(bufA, w3p, bufB, 512, 128);
    scores_kernel<1, 40><<<(N_NODES + 7) / 8, 256>>>(bufB, al3, ar3, 128);
    init_md_kernel<<<NMB1, 256>>>(N_NODES);
    edge_max_kernel<1><<<EB1, 256>>>(src, dst);
    edge_denom_kernel<1><<<EB1, 256>>>(src, dst);
    cudaMemsetAsync(out, 0, (size_t)N_NODES * 40 * sizeof(float));
    edge_agg_kernel<1, 40, 40><<<AGGB, 256>>>(bufB, out, 128, src, dst);
}

// round 3
// speedup vs baseline: 1.1879x; 1.1879x over previous
#include <cuda_runtime.h>
#include <mma.h>
using namespace nvcuda;

#define N_NODES 50000
#define N_PAD   50048          // multiple of 128
#define N_EDGES 400000

// ---------------- device scratch (no allocations allowed) ----------------
__device__ float    g_bufA[(size_t)N_PAD * 512];
__device__ float    g_bufB[(size_t)N_PAD * 512];
__device__ float    g_el[N_NODES * 8];
__device__ float    g_er[N_NODES * 8];
__device__ unsigned g_menc[N_NODES * 8];
__device__ float    g_denom[N_NODES * 8];
__device__ float    g_W3[512 * 128];

__device__ __forceinline__ float lrelu(float x) { return x > 0.f ? x : 0.2f * x; }

// order-preserving float <-> uint encoding (for bit-exact atomic max)
__device__ __forceinline__ unsigned fenc(float x) {
    unsigned u = __float_as_uint(x);
    return (u & 0x80000000u) ? ~u : (u | 0x80000000u);
}
__device__ __forceinline__ float fdec(unsigned e) {
    return (e & 0x80000000u) ? __uint_as_float(e & 0x7fffffffu)
                             : __uint_as_float(~e);
}

// ---------------- W3 pad [512,40] -> [512,128] ----------------
__global__ void padW3_kernel(const float* __restrict__ W3) {
    int i = blockIdx.x * blockDim.x + threadIdx.x;
    if (i < 512 * 128) {
        int r = i >> 7, c = i & 127;
        g_W3[i] = (c < 40) ? W3[r * 40 + c] : 0.f;
    }
}

// ---------------- tf32 WMMA GEMM: C[N_PAD,M] = A[N_PAD,K] * B[K,M] ----------------
// block tile 128x128, k-tile 32; 8 warps, each computes 32 rows x 64 cols (2x4 wmma tiles)
#define LDA_S 40    // 32 + 8 pad (multiple of 4 -> 16B rows)
#define LDB_S 136   // 128 + 8 pad

__global__ __launch_bounds__(256)
void wgemm_kernel(const float* __restrict__ A, const float* __restrict__ B,
                  float* __restrict__ C, int K, int M) {
    __shared__ __align__(16) float As[128 * LDA_S];
    __shared__ __align__(16) float Bs[32 * LDB_S];

    const int t = threadIdx.x;
    const int wid = t >> 5;
    const int wr = wid & 3;        // warp row: rows 32*wr
    const int wc = wid >> 2;       // warp col: cols 64*wc
    const int rowBase = blockIdx.y * 128;
    const int colBase = blockIdx.x * 128;

    wmma::fragment<wmma::accumulator, 16, 16, 8, float> c[2][4];
    #pragma unroll
    for (int i = 0; i < 2; i++)
        #pragma unroll
        for (int j = 0; j < 4; j++) wmma::fill_fragment(c[i][j], 0.f);

    for (int k0 = 0; k0 < K; k0 += 32) {
        // load A tile: 128x32 = 1024 float4
        #pragma unroll
        for (int i = 0; i < 4; i++) {
            int j = t + 256 * i;
            int row = j >> 3, c4 = j & 7;
            float4 v = *reinterpret_cast<const float4*>(
                A + (size_t)(rowBase + row) * K + k0 + 4 * c4);
            *reinterpret_cast<float4*>(As + row * LDA_S + 4 * c4) = v;
        }
        // load B tile: 32x128 = 1024 float4
        #pragma unroll
        for (int i = 0; i < 4; i++) {
            int j = t + 256 * i;
            int row = j >> 5, c4 = j & 31;
            float4 v = *reinterpret_cast<const float4*>(
                B + (size_t)(k0 + row) * M + colBase + 4 * c4);
            *reinterpret_cast<float4*>(Bs + row * LDB_S + 4 * c4) = v;
        }
        __syncthreads();

        #pragma unroll
        for (int kk = 0; kk < 32; kk += 8) {
            wmma::fragment<wmma::matrix_a, 16, 16, 8, wmma::precision::tf32, wmma::row_major> a[2];
            wmma::fragment<wmma::matrix_b, 16, 16, 8, wmma::precision::tf32, wmma::row_major> b[4];
            #pragma unroll
            for (int i = 0; i < 2; i++) {
                wmma::load_matrix_sync(a[i], As + (wr * 32 + 16 * i) * LDA_S + kk, LDA_S);
                #pragma unroll
                for (int x = 0; x < a[i].num_elements; x++)
                    a[i].x[x] = wmma::__float_to_tf32(a[i].x[x]);
            }
            #pragma unroll
            for (int j = 0; j < 4; j++) {
                wmma::load_matrix_sync(b[j], Bs + kk * LDB_S + wc * 64 + 16 * j, LDB_S);
                #pragma unroll
                for (int x = 0; x < b[j].num_elements; x++)
                    b[j].x[x] = wmma::__float_to_tf32(b[j].x[x]);
            }
            #pragma unroll
            for (int i = 0; i < 2; i++)
                #pragma unroll
                for (int j = 0; j < 4; j++)
                    wmma::mma_sync(c[i][j], a[i], b[j], c[i][j]);
        }
        __syncthreads();
    }

    #pragma unroll
    for (int i = 0; i < 2; i++)
        #pragma unroll
        for (int j = 0; j < 4; j++)
            wmma::store_matrix_sync(
                C + (size_t)(rowBase + wr * 32 + 16 * i) * M + colBase + wc * 64 + 16 * j,
                c[i][j], M, wmma::mem_row_major);
}

// ---------------- per-node attention scores el/er ----------------
template <int H, int D>
__global__ void scores_kernel(const float* __restrict__ feat,
                              const float* __restrict__ al,
                              const float* __restrict__ ar, int ldf) {
    int g = (blockIdx.x * blockDim.x + threadIdx.x) >> 5;
    int lane = threadIdx.x & 31;
    if (g >= N_NODES * H) return;
    int n = g / H, h = g % H;
    const float* f = feat + (size_t)n * ldf + h * D;
    float sl = 0.f, sr = 0.f;
    for (int d = lane; d < D; d += 32) {
        float v = f[d];
        sl = fmaf(v, al[h * D + d], sl);
        sr = fmaf(v, ar[h * D + d], sr);
    }
    #pragma unroll
    for (int off = 16; off; off >>= 1) {
        sl += __shfl_down_sync(0xffffffffu, sl, off);
        sr += __shfl_down_sync(0xffffffffu, sr, off);
    }
    if (lane == 0) { g_el[n * H + h] = sl; g_er[n * H + h] = sr; }
}

// ---------------- edge-parallel softmax stats ----------------
__global__ void init_md_kernel(int count) {
    int i = blockIdx.x * blockDim.x + threadIdx.x;
    if (i < count) {
        g_menc[i] = fenc(-1e30f);
        g_denom[i] = 0.f;
    }
}

template <int H>
__global__ void edge_max_kernel(const int* __restrict__ src, const int* __restrict__ dst) {
    int idx = blockIdx.x * blockDim.x + threadIdx.x;
    if (idx >= N_EDGES * H) return;
    int e = idx / H, h = idx - e * H;
    int s = src[e], d = dst[e];
    float v = lrelu(g_el[s * H + h] + g_er[d * H + h]);
    atomicMax(&g_menc[d * H + h], fenc(v));
}

template <int H>
__global__ void edge_denom_kernel(const int* __restrict__ src, const int* __restrict__ dst) {
    int idx = blockIdx.x * blockDim.x + threadIdx.x;
    if (idx >= N_EDGES * H) return;
    int e = idx / H, h = idx - e * H;
    int s = src[e], d = dst[e];
    float v = lrelu(g_el[s * H + h] + g_er[d * H + h]);
    float m = fdec(g_menc[d * H + h]);
    atomicAdd(&g_denom[d * H + h], __expf(v - m));
}

// ---------------- edge-parallel aggregation: warp per edge ----------------
template <int H, int D, int C>
__global__ void edge_agg_kernel(const float* __restrict__ feat,
                                float* __restrict__ out, int ldf,
                                const int* __restrict__ src,
                                const int* __restrict__ dst) {
    int e = (blockIdx.x * blockDim.x + threadIdx.x) >> 5;
    int lane = threadIdx.x & 31;
    if (e >= N_EDGES) return;
    int s = src[e], d = dst[e];

    float alpha = 0.f;
    if (lane < H) {
        float v = lrelu(g_el[s * H + lane] + g_er[d * H + lane]);
        float m = fdec(g_menc[d * H + lane]);
        float den = g_denom[d * H + lane];
        alpha = __expf(v - m) / den;
    }

    const float4* frow = reinterpret_cast<const float4*>(feat + (size_t)s * ldf);
    float4* orow = reinterpret_cast<float4*>(out + (size_t)d * C);
    constexpr int NQ = C / 4;
    #pragma unroll
    for (int q0 = 0; q0 < NQ; q0 += 32) {
        int q = q0 + lane;
        bool ok = (q < NQ);
        int h = ok ? (4 * q) / D : 0;
        float a = __shfl_sync(0xffffffffu, alpha, h);
        if (ok) {
            float4 f = frow[q];
            float4 m4 = make_float4(a * f.x, a * f.y, a * f.z, a * f.w);
            atomicAdd(orow + q, m4);
        }
    }
}

// ---------------- launch ----------------
extern "C" void kernel_launch(void* const* d_in, const int* in_sizes, int n_in,
                              void* d_out, int out_size) {
    const float* features = (const float*)d_in[0];
    const int*   src      = (const int*)d_in[1];
    const int*   dst      = (const int*)d_in[2];
    const float* W1  = (const float*)d_in[3];
    const float* al1 = (const float*)d_in[4];
    const float* ar1 = (const float*)d_in[5];
    const float* W2  = (const float*)d_in[6];
    const float* al2 = (const float*)d_in[7];
    const float* ar2 = (const float*)d_in[8];
    const float* W3  = (const float*)d_in[9];
    const float* al3 = (const float*)d_in[10];
    const float* ar3 = (const float*)d_in[11];
    float* out = (float*)d_out;

    float *bufA, *bufB, *w3p;
    cudaGetSymbolAddress((void**)&bufA, g_bufA);
    cudaGetSymbolAddress((void**)&bufB, g_bufB);
    cudaGetSymbolAddress((void**)&w3p,  g_W3);

    const int EB8  = (N_EDGES * 8 + 255) / 256;
    const int EB1  = (N_EDGES + 255) / 256;
    const int AGGB = (N_EDGES * 32 + 255) / 256;
    const int NMB8 = (N_NODES * 8 + 255) / 256;
    const int NMB1 = (N_NODES + 255) / 256;

    cudaMemcpyAsync(bufA, features, (size_t)N_NODES * 256 * sizeof(float),
                    cudaMemcpyDeviceToDevice);

    // ---- layer 1: 256 -> 8x64 ----
    wgemm_kernel<<<dim3(512 / 128, N_PAD / 128), 256>>>(bufA, W1, bufB, 256, 512);
    scores_kernel<8, 64><<<N_NODES, 256>>>(bufB, al1, ar1, 512);
    init_md_kernel<<<NMB8, 256>>>(N_NODES * 8);
    edge_max_kernel<8><<<EB8, 256>>>(src, dst);
    edge_denom_kernel<8><<<EB8, 256>>>(src, dst);
    cudaMemsetAsync(bufA, 0, (size_t)N_NODES * 512 * sizeof(float));
    edge_agg_kernel<8, 64, 512><<<AGGB, 256>>>(bufB, bufA, 512, src, dst);

    // ---- layer 2: 8x64 -> 8x64 ----
    wgemm_kernel<<<dim3(512 / 128, N_PAD / 128), 256>>>(bufA, W2, bufB, 512, 512);
    scores_kernel<8, 64><<<N_NODES, 256>>>(bufB, al2, ar2, 512);
    init_md_kernel<<<NMB8, 256>>>(N_NODES * 8);
    edge_max_kernel<8><<<EB8, 256>>>(src, dst);
    edge_denom_kernel<8><<<EB8, 256>>>(src, dst);
    cudaMemsetAsync(bufA, 0, (size_t)N_NODES * 512 * sizeof(float));
    edge_agg_kernel<8, 64, 512><<<AGGB, 256>>>(bufB, bufA, 512, src, dst);

    // ---- layer 3: 8x64 -> 40 (padded to 128 cols) ----
    padW3_kernel<<<(512 * 128 + 255) / 256, 256>>>(W3);
    wgemm_kernel<<<dim3(1, N_PAD / 128), 256>>>(bufA, w3p, bufB, 512, 128);
    scores_kernel<1, 40><<<(N_NODES + 7) / 8, 256>>>(bufB, al3, ar3, 128);
    init_md_kernel<<<NMB1, 256>>>(N_NODES);
    edge_max_kernel<1><<<EB1, 256>>>(src, dst);
    edge_denom_kernel<1><<<EB1, 256>>>(src, dst);
    cudaMemsetAsync(out, 0, (size_t)N_NODES * 40 * sizeof(float));
    edge_agg_kernel<1, 40, 40><<<AGGB, 256>>>(bufB, out, 128, src, dst);
}